// round 1
// baseline (speedup 1.0000x reference)
#include <cuda_runtime.h>
#include <cuda_bf16.h>
#include <math.h>

// Problem constants (fixed shapes from reference)
#define BSZ 2
#define NSEQ 4096
#define DMODEL 1024
#define NHEADS 8
#define DH 128
#define RRANK 4
#define KMAX 21

#define M_TOTAL (BSZ * NSEQ)   // 8192

// Scratch buffers (allocation-free rule: __device__ globals)
__device__ float g_xproj[M_TOTAL * DMODEL];   // 32 MB
__device__ float g_concat[M_TOTAL * DMODEL];  // 32 MB

// ---------------------------------------------------------------------------
// SGEMM: C[m][n] = sum_k A[m][k] * B[n][k] + bias[n]
// A: M x K row-major, B: N x K row-major (i.e. C = A @ B^T), all fp32.
// 128x128 block tile, BK=16, 256 threads, 8x8 register tile.
// ---------------------------------------------------------------------------
#define BM 128
#define BN 128
#define BK 16
#define GPAD 4

__global__ __launch_bounds__(256, 2)
void sgemm_nt_bias(const float* __restrict__ A,
                   const float* __restrict__ B,
                   const float* __restrict__ bias,
                   float* __restrict__ C,
                   int M, int N, int K)
{
    __shared__ float As[BK][BM + GPAD];
    __shared__ float Bs[BK][BN + GPAD];

    const int tx = threadIdx.x;   // 0..15 -> N direction
    const int ty = threadIdx.y;   // 0..15 -> M direction
    const int t  = ty * 16 + tx;  // 0..255

    const int m0 = blockIdx.y * BM;
    const int n0 = blockIdx.x * BN;

    float acc[8][8];
#pragma unroll
    for (int i = 0; i < 8; i++)
#pragma unroll
        for (int j = 0; j < 8; j++) acc[i][j] = 0.f;

    const int nkt = K / BK;
    for (int kt = 0; kt < nkt; kt++) {
        const int k0 = kt * BK;
        // Load A and B tiles: 128 rows x 16 cols each = 512 float4 per tile,
        // 2 float4 per thread per tile.
#pragma unroll
        for (int l = 0; l < 2; l++) {
            int id  = t + l * 256;
            int row = id >> 2;      // 0..127
            int c4  = id & 3;       // 0..3 (which float4 within the 16 cols)
            float4 va = *(const float4*)&A[(size_t)(m0 + row) * K + k0 + c4 * 4];
            As[c4 * 4 + 0][row] = va.x;
            As[c4 * 4 + 1][row] = va.y;
            As[c4 * 4 + 2][row] = va.z;
            As[c4 * 4 + 3][row] = va.w;
            float4 vb = *(const float4*)&B[(size_t)(n0 + row) * K + k0 + c4 * 4];
            Bs[c4 * 4 + 0][row] = vb.x;
            Bs[c4 * 4 + 1][row] = vb.y;
            Bs[c4 * 4 + 2][row] = vb.z;
            Bs[c4 * 4 + 3][row] = vb.w;
        }
        __syncthreads();

#pragma unroll
        for (int kk = 0; kk < BK; kk++) {
            float af[8], bf[8];
            *(float4*)&af[0] = *(const float4*)&As[kk][ty * 8];
            *(float4*)&af[4] = *(const float4*)&As[kk][ty * 8 + 4];
            *(float4*)&bf[0] = *(const float4*)&Bs[kk][tx * 8];
            *(float4*)&bf[4] = *(const float4*)&Bs[kk][tx * 8 + 4];
#pragma unroll
            for (int i = 0; i < 8; i++)
#pragma unroll
                for (int j = 0; j < 8; j++)
                    acc[i][j] = fmaf(af[i], bf[j], acc[i][j]);
        }
        __syncthreads();
    }

    // Epilogue: add bias, store.
    float bv[8];
#pragma unroll
    for (int j = 0; j < 8; j++) bv[j] = bias[n0 + tx * 8 + j];

#pragma unroll
    for (int i = 0; i < 8; i++) {
        int m = m0 + ty * 8 + i;
        float4 r0, r1;
        r0.x = acc[i][0] + bv[0]; r0.y = acc[i][1] + bv[1];
        r0.z = acc[i][2] + bv[2]; r0.w = acc[i][3] + bv[3];
        r1.x = acc[i][4] + bv[4]; r1.y = acc[i][5] + bv[5];
        r1.z = acc[i][6] + bv[6]; r1.w = acc[i][7] + bv[7];
        *(float4*)&C[(size_t)m * N + n0 + tx * 8]     = r0;
        *(float4*)&C[(size_t)m * N + n0 + tx * 8 + 4] = r1;
    }
}

// ---------------------------------------------------------------------------
// Middle stage (per head): dynamic-kernel windowed mixing.
// o[b,n,h,d] = alpha * sum_r c[b,n,r]*V[h,r,d]*(sum_j A[h,r,j]*w_j)
//            + (1-alpha) * sum_j base[h,j,d]*w_j
// where w_j = xproj[b, n+j-pad, h, d] (zero outside [0,N)).
// One block = 128 threads (d) x 32 token positions for one (b,h).
// ---------------------------------------------------------------------------
#define TILE_N 32

template<int K>
__global__ __launch_bounds__(128)
void dka_mid(const float* __restrict__ Wc,
             const float* __restrict__ Aar,
             const float* __restrict__ Var,
             const float* __restrict__ basep,
             const float* __restrict__ alphas,
             int head0)
{
    constexpr int PAD  = K / 2;
    constexpr int ROWS = TILE_N + K - 1;

    __shared__ float sh[ROWS][DH + 1];
    __shared__ float A_sh[RRANK][K];
    __shared__ float c_sh[TILE_N][RRANK];

    const int d  = threadIdx.x;            // 0..127
    const int h  = head0 + blockIdx.y;
    const int b  = blockIdx.z;
    const int n0 = blockIdx.x * TILE_N;

    const float* xp = g_xproj + (size_t)b * NSEQ * DMODEL + h * DH;

    // Stage the window tile.
#pragma unroll
    for (int i = 0; i < ROWS; i++) {
        int n = n0 + i - PAD;
        sh[i][d] = (n >= 0 && n < NSEQ) ? xp[(size_t)n * DMODEL + d] : 0.f;
    }
    if (d < RRANK * K) {
        int r = d / K, j = d % K;
        A_sh[r][j] = Aar[(size_t)h * RRANK * KMAX + r * KMAX + j];
    }
    __syncthreads();

    // c[nl][r] = sum_d sh[nl+PAD][d] * Wc[h][d][r]  (128 tasks, one per thread)
    {
        int nl = d >> 2, r = d & 3;
        const float* wc = Wc + (size_t)h * DH * RRANK + r;
        float s = 0.f;
#pragma unroll 8
        for (int dd = 0; dd < DH; dd++)
            s = fmaf(sh[nl + PAD][dd], wc[dd * RRANK], s);
        c_sh[nl][r] = s;
    }
    __syncthreads();

    const float alpha = 1.f / (1.f + expf(-alphas[h]));
    const float beta  = 1.f - alpha;

    float baser[K];
#pragma unroll
    for (int j = 0; j < K; j++)
        baser[j] = basep[((size_t)h * KMAX + j) * DH + d];
    float Vr[RRANK];
#pragma unroll
    for (int r = 0; r < RRANK; r++)
        Vr[r] = Var[((size_t)h * RRANK + r) * DH + d];

    float* outp = g_concat + (size_t)b * NSEQ * DMODEL + h * DH + d;

#pragma unroll 4
    for (int nl = 0; nl < TILE_N; nl++) {
        float tb = 0.f, s0 = 0.f, s1 = 0.f, s2 = 0.f, s3 = 0.f;
#pragma unroll
        for (int j = 0; j < K; j++) {
            float xv = sh[nl + j][d];
            tb = fmaf(baser[j],  xv, tb);
            s0 = fmaf(A_sh[0][j], xv, s0);
            s1 = fmaf(A_sh[1][j], xv, s1);
            s2 = fmaf(A_sh[2][j], xv, s2);
            s3 = fmaf(A_sh[3][j], xv, s3);
        }
        float dynsum = c_sh[nl][0] * Vr[0] * s0
                     + c_sh[nl][1] * Vr[1] * s1
                     + c_sh[nl][2] * Vr[2] * s2
                     + c_sh[nl][3] * Vr[3] * s3;
        outp[(size_t)(n0 + nl) * DMODEL] = alpha * dynsum + beta * tb;
    }
}

// ---------------------------------------------------------------------------
// Launch
// ---------------------------------------------------------------------------
extern "C" void kernel_launch(void* const* d_in, const int* in_sizes, int n_in,
                              void* d_out, int out_size)
{
    const float* x      = (const float*)d_in[0];
    const float* W_in   = (const float*)d_in[1];
    const float* b_in   = (const float*)d_in[2];
    const float* W_out  = (const float*)d_in[3];
    const float* b_out  = (const float*)d_in[4];
    const float* Wc     = (const float*)d_in[5];
    const float* A      = (const float*)d_in[6];
    const float* V      = (const float*)d_in[7];
    const float* basep  = (const float*)d_in[8];
    const float* alphas = (const float*)d_in[9];
    float* out = (float*)d_out;

    float* xproj  = nullptr;
    float* concat = nullptr;
    cudaGetSymbolAddress((void**)&xproj,  g_xproj);
    cudaGetSymbolAddress((void**)&concat, g_concat);

    dim3 gblk(16, 16);
    dim3 ggrid(DMODEL / BN, M_TOTAL / BM);  // (8, 64)

    // GEMM 1: x_proj = x @ W_in^T + b_in
    sgemm_nt_bias<<<ggrid, gblk>>>(x, W_in, b_in, xproj, M_TOTAL, DMODEL, DMODEL);

    // Middle stage: 4 templated launches (heads paired by window size)
    dim3 mgrid(NSEQ / TILE_N, 2, BSZ);      // (128, 2, 2)
    dka_mid<3 ><<<mgrid, 128>>>(Wc, A, V, basep, alphas, 0);
    dka_mid<7 ><<<mgrid, 128>>>(Wc, A, V, basep, alphas, 2);
    dka_mid<11><<<mgrid, 128>>>(Wc, A, V, basep, alphas, 4);
    dka_mid<21><<<mgrid, 128>>>(Wc, A, V, basep, alphas, 6);

    // GEMM 2: out = concat @ W_out^T + b_out
    sgemm_nt_bias<<<ggrid, gblk>>>(concat, W_out, b_out, out, M_TOTAL, DMODEL, DMODEL);
}

// round 3
// speedup vs baseline: 1.7746x; 1.7746x over previous
#include <cuda_runtime.h>
#include <cuda_bf16.h>
#include <cstdint>
#include <math.h>

// ---------------------------------------------------------------- constants
#define BSZ 2
#define NSEQ 4096
#define DMODEL 1024
#define NHEADS 8
#define DH 128
#define RRANK 4
#define KMAX 21
#define M_TOTAL (BSZ * NSEQ)   // 8192

// ---------------------------------------------------------------- scratch
__device__ float         g_xproj[M_TOTAL * DMODEL];   // 32 MB fp32
__device__ __nv_bfloat16 g_xhi[M_TOTAL * DMODEL];
__device__ __nv_bfloat16 g_xlo[M_TOTAL * DMODEL];
__device__ __nv_bfloat16 g_wihi[DMODEL * DMODEL];
__device__ __nv_bfloat16 g_wilo[DMODEL * DMODEL];
__device__ __nv_bfloat16 g_wohi[DMODEL * DMODEL];
__device__ __nv_bfloat16 g_wolo[DMODEL * DMODEL];
__device__ __nv_bfloat16 g_chi[M_TOTAL * DMODEL];
__device__ __nv_bfloat16 g_clo[M_TOTAL * DMODEL];

// ---------------------------------------------------------------- helpers (base-ISA only)
__device__ __forceinline__ uint32_t smem_u32(const void* p) {
    uint32_t a;
    asm("{ .reg .u64 t; cvta.to.shared.u64 t, %1; cvt.u32.u64 %0, t; }" : "=r"(a) : "l"(p));
    return a;
}
__device__ __forceinline__ void cp_async16(uint32_t dst, const void* src) {
    asm volatile("cp.async.cg.shared.global [%0], [%1], 16;" :: "r"(dst), "l"(src));
}
__device__ __forceinline__ void ldm4(uint32_t* r, uint32_t addr) {
    asm volatile("ldmatrix.sync.aligned.m8n8.x4.shared.b16 {%0,%1,%2,%3}, [%4];"
                 : "=r"(r[0]), "=r"(r[1]), "=r"(r[2]), "=r"(r[3]) : "r"(addr));
}
__device__ __forceinline__ void mma_bf16(float* d, const uint32_t* a, const uint32_t* b) {
    asm volatile(
        "mma.sync.aligned.m16n8k16.row.col.f32.bf16.bf16.f32 "
        "{%0,%1,%2,%3}, {%4,%5,%6,%7}, {%8,%9}, {%0,%1,%2,%3};"
        : "+f"(d[0]), "+f"(d[1]), "+f"(d[2]), "+f"(d[3])
        : "r"(a[0]), "r"(a[1]), "r"(a[2]), "r"(a[3]), "r"(b[0]), "r"(b[1]));
}

// ---------------------------------------------------------------- split conversion: v -> (bf16 hi, bf16 lo)
__global__ __launch_bounds__(256)
void split_bf16(const float* __restrict__ s,
                __nv_bfloat16* __restrict__ hi,
                __nv_bfloat16* __restrict__ lo, int n4)
{
    int i = blockIdx.x * blockDim.x + threadIdx.x;
    if (i >= n4) return;
    float4 v = ((const float4*)s)[i];
    __nv_bfloat16 h0 = __float2bfloat16(v.x), h1 = __float2bfloat16(v.y);
    __nv_bfloat16 h2 = __float2bfloat16(v.z), h3 = __float2bfloat16(v.w);
    __nv_bfloat16 l0 = __float2bfloat16(v.x - __bfloat162float(h0));
    __nv_bfloat16 l1 = __float2bfloat16(v.y - __bfloat162float(h1));
    __nv_bfloat16 l2 = __float2bfloat16(v.z - __bfloat162float(h2));
    __nv_bfloat16 l3 = __float2bfloat16(v.w - __bfloat162float(h3));
    ((__nv_bfloat162*)hi)[2 * i]     = __nv_bfloat162(h0, h1);
    ((__nv_bfloat162*)hi)[2 * i + 1] = __nv_bfloat162(h2, h3);
    ((__nv_bfloat162*)lo)[2 * i]     = __nv_bfloat162(l0, l1);
    ((__nv_bfloat162*)lo)[2 * i + 1] = __nv_bfloat162(l2, l3);
}

// ---------------------------------------------------------------- mma.sync GEMM: C = A @ B^T + bias (bf16 hi/lo x3)
// A: M x 1024 (hi/lo bf16), B: N x 1024 (hi/lo bf16), C: fp32.
// CTA tile 128x128, BK=16, 4-stage cp.async pipeline, 8 warps @ 64x32.
#define BM 128
#define BN 128
#define NKT 64                 // 1024 / 16
#define PITCH 48               // bytes per smem row (16 bf16 + 8 pad)
#define MATB (128 * PITCH)     // 6144 B per matrix per stage
#define STAGEB (4 * MATB)      // Ahi, Alo, Bhi, Blo
#define SMEM_GEMM (4 * STAGEB) // 98304 B

__global__ __launch_bounds__(256, 1)
void gemm_mma(const __nv_bfloat16* __restrict__ Ahi, const __nv_bfloat16* __restrict__ Alo,
              const __nv_bfloat16* __restrict__ Bhi, const __nv_bfloat16* __restrict__ Blo,
              const float* __restrict__ bias, float* __restrict__ C)
{
    extern __shared__ char smem[];
    const uint32_t sb = smem_u32(smem);
    const int tid  = threadIdx.x;
    const int lane = tid & 31;
    const int wid  = tid >> 5;
    const int m0 = blockIdx.y * BM;
    const int n0 = blockIdx.x * BN;
    const int wm = (wid >> 2) * 64;   // warp m-offset in tile
    const int wn = (wid & 3) * 32;    // warp n-offset in tile

    const __nv_bfloat16* srcs[4] = {
        Ahi + (size_t)m0 * DMODEL, Alo + (size_t)m0 * DMODEL,
        Bhi + (size_t)n0 * DMODEL, Blo + (size_t)n0 * DMODEL };

    // per-thread fixed part of the load pattern: 4 chunks of 16B
    auto load_stage = [&](int kt, int s) {
        const uint32_t base = sb + s * STAGEB;
#pragma unroll
        for (int i = 0; i < 4; i++) {
            int g    = tid + i * 256;       // 0..1023
            int mat  = g >> 8;              // 0..3
            int rem  = g & 255;
            int row  = rem >> 1;            // 0..127
            int half = rem & 1;             // which 16B of the 32B row
            const __nv_bfloat16* src = srcs[mat] + (size_t)row * DMODEL + kt * 16 + half * 8;
            cp_async16(base + mat * MATB + row * PITCH + half * 16, src);
        }
        asm volatile("cp.async.commit_group;" ::: "memory");
    };

    float acc[4][4][4];
#pragma unroll
    for (int a = 0; a < 4; a++)
#pragma unroll
        for (int b = 0; b < 4; b++)
#pragma unroll
            for (int c = 0; c < 4; c++) acc[a][b][c] = 0.f;

    load_stage(0, 0);
    load_stage(1, 1);
    load_stage(2, 2);

    // precomputed ldmatrix lane offsets
    const uint32_t a_row = (lane & 15);
    const uint32_t a_koff = (lane >> 4) * 16;
    const uint32_t b_row = (lane & 7) + ((lane >> 4) << 3);
    const uint32_t b_koff = ((lane >> 3) & 1) * 16;

    for (int kt = 0; kt < NKT; kt++) {
        asm volatile("cp.async.wait_group 2;" ::: "memory");
        __syncthreads();

        if (kt + 3 < NKT) load_stage(kt + 3, (kt + 3) & 3);
        else              asm volatile("cp.async.commit_group;" ::: "memory");

        const uint32_t stb  = sb + (kt & 3) * STAGEB;
        const uint32_t sAhi = stb;
        const uint32_t sAlo = stb + MATB;
        const uint32_t sBhi = stb + 2 * MATB;
        const uint32_t sBlo = stb + 3 * MATB;

        uint32_t ahi[4][4], alo[4][4], bhi[2][4], blo[2][4];
#pragma unroll
        for (int mi = 0; mi < 4; mi++) {
            uint32_t off = (wm + mi * 16 + a_row) * PITCH + a_koff;
            ldm4(ahi[mi], sAhi + off);
            ldm4(alo[mi], sAlo + off);
        }
#pragma unroll
        for (int t = 0; t < 2; t++) {
            uint32_t off = (wn + t * 16 + b_row) * PITCH + b_koff;
            ldm4(bhi[t], sBhi + off);
            ldm4(blo[t], sBlo + off);
        }

#pragma unroll
        for (int mi = 0; mi < 4; mi++)
#pragma unroll
            for (int ni = 0; ni < 4; ni++) {
                const int t = ni >> 1, p = (ni & 1) * 2;
                uint32_t bh[2] = {bhi[t][p], bhi[t][p + 1]};
                uint32_t bl[2] = {blo[t][p], blo[t][p + 1]};
                mma_bf16(acc[mi][ni], ahi[mi], bh);   // hi*hi
                mma_bf16(acc[mi][ni], ahi[mi], bl);   // hi*lo
                mma_bf16(acc[mi][ni], alo[mi], bh);   // lo*hi
            }
    }

    // epilogue: bias + store
    const float* bs = bias + n0 + wn;
    float* Cb = C + (size_t)(m0 + wm) * DMODEL + n0 + wn;
#pragma unroll
    for (int mi = 0; mi < 4; mi++) {
        int r0 = mi * 16 + (lane >> 2);
#pragma unroll
        for (int ni = 0; ni < 4; ni++) {
            int c = ni * 8 + (lane & 3) * 2;
            float b0 = bs[c], b1 = bs[c + 1];
            float2 v0 = {acc[mi][ni][0] + b0, acc[mi][ni][1] + b1};
            float2 v1 = {acc[mi][ni][2] + b0, acc[mi][ni][3] + b1};
            *(float2*)&Cb[(size_t)r0 * DMODEL + c]       = v0;
            *(float2*)&Cb[(size_t)(r0 + 8) * DMODEL + c] = v1;
        }
    }
}

// ---------------------------------------------------------------- middle stage (fused over all heads)
#define TILE_N 32
#define MAXROWS (TILE_N + KMAX - 1)   // 52

template<int K>
__device__ __forceinline__ void dka_impl(int h, int b, int n0, int d,
    const float* __restrict__ Wc, const float* __restrict__ Aar,
    const float* __restrict__ Var, const float* __restrict__ basep,
    const float* __restrict__ alphas,
    float (*sh)[DH + 1], float* A_sh, float (*c_sh)[RRANK])
{
    constexpr int PAD  = K / 2;
    constexpr int ROWS = TILE_N + K - 1;

    const float* xp = g_xproj + (size_t)b * NSEQ * DMODEL + h * DH;
#pragma unroll
    for (int i = 0; i < ROWS; i++) {
        int n = n0 + i - PAD;
        sh[i][d] = (n >= 0 && n < NSEQ) ? xp[(size_t)n * DMODEL + d] : 0.f;
    }
    if (d < RRANK * K) {
        int r = d / K, j = d % K;
        A_sh[r * K + j] = Aar[(size_t)h * RRANK * KMAX + r * KMAX + j];
    }
    __syncthreads();

    {   // c[nl][r] = <window_center, Wc[:,r]>
        int nl = d >> 2, r = d & 3;
        const float* wc = Wc + (size_t)h * DH * RRANK + r;
        float s = 0.f;
#pragma unroll 8
        for (int dd = 0; dd < DH; dd++)
            s = fmaf(sh[nl + PAD][dd], wc[dd * RRANK], s);
        c_sh[nl][r] = s;
    }
    __syncthreads();

    const float alpha = 1.f / (1.f + expf(-alphas[h]));
    const float beta  = 1.f - alpha;

    float baser[K];
#pragma unroll
    for (int j = 0; j < K; j++)
        baser[j] = basep[((size_t)h * KMAX + j) * DH + d];
    float Vr[RRANK];
#pragma unroll
    for (int r = 0; r < RRANK; r++)
        Vr[r] = Var[((size_t)h * RRANK + r) * DH + d];

    __nv_bfloat16* ohi = g_chi + (size_t)b * NSEQ * DMODEL + h * DH + d;
    __nv_bfloat16* olo = g_clo + (size_t)b * NSEQ * DMODEL + h * DH + d;

#pragma unroll 4
    for (int nl = 0; nl < TILE_N; nl++) {
        float tb = 0.f, s0 = 0.f, s1 = 0.f, s2 = 0.f, s3 = 0.f;
#pragma unroll
        for (int j = 0; j < K; j++) {
            float xv = sh[nl + j][d];
            tb = fmaf(baser[j],        xv, tb);
            s0 = fmaf(A_sh[0 * K + j], xv, s0);
            s1 = fmaf(A_sh[1 * K + j], xv, s1);
            s2 = fmaf(A_sh[2 * K + j], xv, s2);
            s3 = fmaf(A_sh[3 * K + j], xv, s3);
        }
        float dynsum = c_sh[nl][0] * Vr[0] * s0 + c_sh[nl][1] * Vr[1] * s1
                     + c_sh[nl][2] * Vr[2] * s2 + c_sh[nl][3] * Vr[3] * s3;
        float val = alpha * dynsum + beta * tb;
        __nv_bfloat16 hv = __float2bfloat16(val);
        size_t off = (size_t)(n0 + nl) * DMODEL;
        ohi[off] = hv;
        olo[off] = __float2bfloat16(val - __bfloat162float(hv));
    }
}

__global__ __launch_bounds__(128)
void dka_mid_fused(const float* __restrict__ Wc, const float* __restrict__ Aar,
                   const float* __restrict__ Var, const float* __restrict__ basep,
                   const float* __restrict__ alphas)
{
    __shared__ float sh[MAXROWS][DH + 1];
    __shared__ float A_sh[RRANK * KMAX];
    __shared__ float c_sh[TILE_N][RRANK];

    const int d  = threadIdx.x;
    const int h  = blockIdx.y;
    const int b  = blockIdx.z;
    const int n0 = blockIdx.x * TILE_N;

    switch (h >> 1) {
        case 0: dka_impl<3 >(h, b, n0, d, Wc, Aar, Var, basep, alphas, sh, A_sh, c_sh); break;
        case 1: dka_impl<7 >(h, b, n0, d, Wc, Aar, Var, basep, alphas, sh, A_sh, c_sh); break;
        case 2: dka_impl<11>(h, b, n0, d, Wc, Aar, Var, basep, alphas, sh, A_sh, c_sh); break;
        default: dka_impl<21>(h, b, n0, d, Wc, Aar, Var, basep, alphas, sh, A_sh, c_sh); break;
    }
}

// ---------------------------------------------------------------- launch
extern "C" void kernel_launch(void* const* d_in, const int* in_sizes, int n_in,
                              void* d_out, int out_size)
{
    const float* x      = (const float*)d_in[0];
    const float* W_in   = (const float*)d_in[1];
    const float* b_in   = (const float*)d_in[2];
    const float* W_out  = (const float*)d_in[3];
    const float* b_out  = (const float*)d_in[4];
    const float* Wc     = (const float*)d_in[5];
    const float* A      = (const float*)d_in[6];
    const float* V      = (const float*)d_in[7];
    const float* basep  = (const float*)d_in[8];
    const float* alphas = (const float*)d_in[9];
    float* out = (float*)d_out;

    float *xproj;
    __nv_bfloat16 *xhi, *xlo, *wihi, *wilo, *wohi, *wolo, *chi, *clo;
    cudaGetSymbolAddress((void**)&xproj, g_xproj);
    cudaGetSymbolAddress((void**)&xhi,  g_xhi);  cudaGetSymbolAddress((void**)&xlo,  g_xlo);
    cudaGetSymbolAddress((void**)&wihi, g_wihi); cudaGetSymbolAddress((void**)&wilo, g_wilo);
    cudaGetSymbolAddress((void**)&wohi, g_wohi); cudaGetSymbolAddress((void**)&wolo, g_wolo);
    cudaGetSymbolAddress((void**)&chi,  g_chi);  cudaGetSymbolAddress((void**)&clo,  g_clo);

    cudaFuncSetAttribute(gemm_mma, cudaFuncAttributeMaxDynamicSharedMemorySize, SMEM_GEMM);

    // 1. split conversions
    int n4x = M_TOTAL * DMODEL / 4;
    split_bf16<<<n4x / 256, 256>>>(x, xhi, xlo, n4x);
    int n4w = DMODEL * DMODEL / 4;
    split_bf16<<<n4w / 256, 256>>>(W_in,  wihi, wilo, n4w);
    split_bf16<<<n4w / 256, 256>>>(W_out, wohi, wolo, n4w);

    dim3 ggrid(DMODEL / BN, M_TOTAL / BM);   // (8, 64)

    // 2. GEMM1: xproj = x @ W_in^T + b_in
    gemm_mma<<<ggrid, 256, SMEM_GEMM>>>(xhi, xlo, wihi, wilo, b_in, xproj);

    // 3. middle stage (fused heads), writes concat as bf16 hi/lo
    dka_mid_fused<<<dim3(NSEQ / TILE_N, NHEADS, BSZ), 128>>>(Wc, A, V, basep, alphas);

    // 4. GEMM2: out = concat @ W_out^T + b_out
    gemm_mma<<<ggrid, 256, SMEM_GEMM>>>(chi, clo, wohi, wolo, b_out, out);
}